// round 2
// baseline (speedup 1.0000x reference)
#include <cuda_runtime.h>
#include <cstdint>

#define N_TOK 16384
#define H 1024
#define D_EXP 512
#define S_INT 1024
#define NEXP 8
#define VOCAB 50257
#define BM 128
#define BN 128
#define BK 8
#define NP_MAX (N_TOK + NEXP * BM)   // 17408 padded rows

// ---------------- scratch (static device globals; no allocation) -------------
__device__ int g_counts[NEXP];
__device__ int g_cursor[NEXP];
__device__ int g_off[NEXP + 1];
__device__ int g_perm[NP_MAX];

__device__ __align__(16) float g_a[N_TOK * S_INT];   // shared gate -> shared act
__device__ __align__(16) float g_b[N_TOK * S_INT];   // shared up; later routed gate -> routed act
__device__ __align__(16) float g_c[NP_MAX * D_EXP];  // routed up

// ---------------- routing kernels -------------------------------------------
__device__ __forceinline__ int expert_of(int t) {
    t = t < 0 ? 0 : (t > VOCAB - 1 ? VOCAB - 1 : t);
    return t & (NEXP - 1);
}

__global__ void k_reset() {
    int i = blockIdx.x * blockDim.x + threadIdx.x;
    if (i < NP_MAX) g_perm[i] = -1;
    if (i < NEXP) { g_counts[i] = 0; g_cursor[i] = 0; }
}

__global__ void k_hist(const int* __restrict__ tok) {
    int i = blockIdx.x * blockDim.x + threadIdx.x;
    if (i < N_TOK) atomicAdd(&g_counts[expert_of(tok[i])], 1);
}

__global__ void k_off() {
    g_off[0] = 0;
    for (int e = 0; e < NEXP; e++)
        g_off[e + 1] = g_off[e] + ((g_counts[e] + BM - 1) / BM) * BM;
}

__global__ void k_scatter(const int* __restrict__ tok) {
    int i = blockIdx.x * blockDim.x + threadIdx.x;
    if (i < N_TOK) {
        int e = expert_of(tok[i]);
        int p = atomicAdd(&g_cursor[e], 1);
        g_perm[g_off[e] + p] = i;
    }
}

// ---------------- fused silu(g) * u ------------------------------------------
__global__ void k_silu_mul(const float* __restrict__ G, const float* __restrict__ U,
                           float* __restrict__ O, int n4) {
    int i = blockIdx.x * blockDim.x + threadIdx.x;
    if (i >= n4) return;
    float4 g = reinterpret_cast<const float4*>(G)[i];
    float4 u = reinterpret_cast<const float4*>(U)[i];
    float4 o;
    o.x = g.x / (1.0f + __expf(-g.x)) * u.x;
    o.y = g.y / (1.0f + __expf(-g.y)) * u.y;
    o.z = g.z / (1.0f + __expf(-g.z)) * u.z;
    o.w = g.w / (1.0f + __expf(-g.w)) * u.w;
    reinterpret_cast<float4*>(O)[i] = o;
}

// ---------------- SGEMM 128x128x8, fp32 via packed fma.rn.f32x2 --------------
// GA: gather A rows through g_perm (rows < 0 load zeros)
// SC: scatter-add C rows through g_perm (rows < 0 skipped)
// EX: B is per-expert [K,Nw] slab selected via g_off; tiles past g_off[8] exit
template <bool GA, bool SC, bool EX>
__global__ void __launch_bounds__(256, 2)
sgemm(const float* __restrict__ A, const float* __restrict__ Bb,
      float* __restrict__ C, int Nw, int K)
{
    __shared__ __align__(16) float As[BK][BM];
    __shared__ __align__(16) float Bs[BK][BN];

    const int tid  = threadIdx.x;
    const int row0 = blockIdx.y * BM;
    const int col0 = blockIdx.x * BN;

    const float* B = Bb;
    if (EX) {
        if (row0 >= g_off[NEXP]) return;
        int e = 0;
#pragma unroll
        for (int i = 1; i < NEXP; i++)
            if (row0 >= g_off[i]) e = i;
        B += (size_t)e * K * Nw;
    }

    // A-tile load mapping: thread -> (row, 4 consecutive k)
    const int a_row = tid >> 1;
    const int a_k4  = (tid & 1) * 4;
    long a_off = 0;
    bool a_ok  = true;
    if (GA) {
        int gr = g_perm[row0 + a_row];
        a_ok   = (gr >= 0);
        a_off  = (long)(a_ok ? gr : 0) * K;
    } else {
        a_off = (long)(row0 + a_row) * K;
    }

    // B-tile load mapping: thread -> (k-row, 4 consecutive cols)
    const int b_col = (tid & 31) * 4;
    const int b_k   = tid >> 5;
    const float* Bp = B + (size_t)b_k * Nw + col0 + b_col;

    const int ty = tid >> 4;
    const int tx = tid & 15;

    unsigned long long acc[8][4];
#pragma unroll
    for (int i = 0; i < 8; i++)
#pragma unroll
        for (int j = 0; j < 4; j++) acc[i][j] = 0ull;

    for (int kt = 0; kt < K; kt += BK) {
        float4 av = make_float4(0.f, 0.f, 0.f, 0.f);
        if (a_ok) av = *reinterpret_cast<const float4*>(A + a_off + kt + a_k4);
        As[a_k4 + 0][a_row] = av.x;
        As[a_k4 + 1][a_row] = av.y;
        As[a_k4 + 2][a_row] = av.z;
        As[a_k4 + 3][a_row] = av.w;
        *reinterpret_cast<float4*>(&Bs[b_k][b_col]) =
            *reinterpret_cast<const float4*>(Bp + (size_t)kt * Nw);
        __syncthreads();

#pragma unroll
        for (int kk = 0; kk < BK; kk++) {
            float4 a0 = *reinterpret_cast<const float4*>(&As[kk][ty * 8]);
            float4 a1 = *reinterpret_cast<const float4*>(&As[kk][ty * 8 + 4]);
            ulonglong2 bq0 = *reinterpret_cast<const ulonglong2*>(&Bs[kk][tx * 8]);
            ulonglong2 bq1 = *reinterpret_cast<const ulonglong2*>(&Bs[kk][tx * 8 + 4]);
            unsigned long long bp[4] = {bq0.x, bq0.y, bq1.x, bq1.y};
            float aa[8] = {a0.x, a0.y, a0.z, a0.w, a1.x, a1.y, a1.z, a1.w};
#pragma unroll
            for (int i = 0; i < 8; i++) {
                unsigned long long ad;
                unsigned int au = __float_as_uint(aa[i]);
                asm("mov.b64 %0, {%1, %1};" : "=l"(ad) : "r"(au));
#pragma unroll
                for (int j = 0; j < 4; j++)
                    asm("fma.rn.f32x2 %0, %1, %2, %3;"
                        : "=l"(acc[i][j])
                        : "l"(ad), "l"(bp[j]), "l"(acc[i][j]));
            }
        }
        __syncthreads();
    }

#pragma unroll
    for (int i = 0; i < 8; i++) {
        int r = row0 + ty * 8 + i;
        if (SC) {
            int gr = g_perm[r];
            if (gr < 0) continue;
            r = gr;
        }
        float* Cp = C + (size_t)r * Nw + col0 + tx * 8;
        float2 v0 = *reinterpret_cast<float2*>(&acc[i][0]);
        float2 v1 = *reinterpret_cast<float2*>(&acc[i][1]);
        float2 v2 = *reinterpret_cast<float2*>(&acc[i][2]);
        float2 v3 = *reinterpret_cast<float2*>(&acc[i][3]);
        if (SC) {
            float4 o0 = *reinterpret_cast<float4*>(Cp);
            float4 o1 = *reinterpret_cast<float4*>(Cp + 4);
            o0.x += v0.x; o0.y += v0.y; o0.z += v1.x; o0.w += v1.y;
            o1.x += v2.x; o1.y += v2.y; o1.z += v3.x; o1.w += v3.y;
            *reinterpret_cast<float4*>(Cp)     = o0;
            *reinterpret_cast<float4*>(Cp + 4) = o1;
        } else {
            *reinterpret_cast<float4*>(Cp)     = make_float4(v0.x, v0.y, v1.x, v1.y);
            *reinterpret_cast<float4*>(Cp + 4) = make_float4(v2.x, v2.y, v3.x, v3.y);
        }
    }
}

// ---------------- launch ------------------------------------------------------
extern "C" void kernel_launch(void* const* d_in, const int* in_sizes, int n_in,
                              void* d_out, int out_size)
{
    const float* x   = (const float*)d_in[0];
    const int*   tok = (const int*)d_in[1];
    const float* gw  = (const float*)d_in[2];   // [8,1024,512]
    const float* uw  = (const float*)d_in[3];   // [8,1024,512]
    const float* dw  = (const float*)d_in[4];   // [8,512,1024]
    const float* sgw = (const float*)d_in[5];   // [1024,1024]
    const float* suw = (const float*)d_in[6];   // [1024,1024]
    const float* sdw = (const float*)d_in[7];   // [1024,1024]
    float* out = (float*)d_out;

    float *ga, *gb, *gc;
    cudaGetSymbolAddress((void**)&ga, g_a);
    cudaGetSymbolAddress((void**)&gb, g_b);
    cudaGetSymbolAddress((void**)&gc, g_c);

    // routing: reset -> histogram -> padded offsets -> scatter
    k_reset<<<(NP_MAX + 255) / 256, 256>>>();
    k_hist<<<(N_TOK + 255) / 256, 256>>>(tok);
    k_off<<<1, 1>>>();
    k_scatter<<<(N_TOK + 255) / 256, 256>>>(tok);

    // shared branch: g = x@Wsg ; u = x@Wsu ; act = silu(g)*u ; out = act@Wsd
    dim3 gs(S_INT / BN, N_TOK / BM);
    sgemm<false, false, false><<<gs, 256>>>(x, sgw, ga, S_INT, H);
    sgemm<false, false, false><<<gs, 256>>>(x, suw, gb, S_INT, H);
    k_silu_mul<<<(N_TOK * S_INT / 4 + 255) / 256, 256>>>(ga, gb, ga, N_TOK * S_INT / 4);
    dim3 gd(H / BN, N_TOK / BM);
    sgemm<false, false, false><<<gd, 256>>>(ga, sdw, out, H, S_INT);

    // routed branch on permuted (expert-grouped, padded) rows
    dim3 gr(D_EXP / BN, NP_MAX / BM);
    sgemm<true, false, true><<<gr, 256>>>(x, gw, gb, D_EXP, H);   // gate -> gb
    sgemm<true, false, true><<<gr, 256>>>(x, uw, gc, D_EXP, H);   // up   -> gc
    k_silu_mul<<<(NP_MAX * D_EXP / 4 + 255) / 256, 256>>>(gb, gc, gb, NP_MAX * D_EXP / 4);
    dim3 gdd(H / BN, NP_MAX / BM);
    sgemm<false, true, true><<<gdd, 256>>>(gb, dw, out, H, D_EXP); // out[perm] += act@Wd[e]
}

// round 7
// speedup vs baseline: 1.9808x; 1.9808x over previous
#include <cuda_runtime.h>
#include <cuda_bf16.h>
#include <cstdint>

#define N_TOK 16384
#define H     1024
#define D_EXP 512
#define S_INT 1024
#define NEXP  8
#define VOCAB 50257
#define NP_MAX (N_TOK + NEXP*128)

#define BM 128
#define BN 128
#define BK 32
#define LDSB 80                 // smem bytes per row: 32 bf16 + 16B pad (conflict-free ldmatrix)
#define TILE_B (128*LDSB)       // 10240 B per operand tile
#define STG_B  (4*TILE_B)       // Ah,Al,Bh,Bl
#define NSTG 3
#define SMEM_BYTES (NSTG*STG_B) // 122880

// ---------------- routing scratch --------------------------------------------
__device__ int g_counts[NEXP];
__device__ int g_cursor[NEXP];
__device__ int g_off[NEXP+1];
__device__ int g_perm[NP_MAX];

// ---------------- split operands / intermediates -----------------------------
__device__ __align__(16) __nv_bfloat16 g_xh[(size_t)N_TOK*H];
__device__ __align__(16) __nv_bfloat16 g_xl[(size_t)N_TOK*H];
__device__ __align__(16) __nv_bfloat16 g_gth[(size_t)NEXP*D_EXP*H];
__device__ __align__(16) __nv_bfloat16 g_gtl[(size_t)NEXP*D_EXP*H];
__device__ __align__(16) __nv_bfloat16 g_uth[(size_t)NEXP*D_EXP*H];
__device__ __align__(16) __nv_bfloat16 g_utl[(size_t)NEXP*D_EXP*H];
__device__ __align__(16) __nv_bfloat16 g_dth[(size_t)NEXP*H*D_EXP];
__device__ __align__(16) __nv_bfloat16 g_dtl[(size_t)NEXP*H*D_EXP];
__device__ __align__(16) __nv_bfloat16 g_sgth[(size_t)H*S_INT];
__device__ __align__(16) __nv_bfloat16 g_sgtl[(size_t)H*S_INT];
__device__ __align__(16) __nv_bfloat16 g_suth[(size_t)H*S_INT];
__device__ __align__(16) __nv_bfloat16 g_sutl[(size_t)H*S_INT];
__device__ __align__(16) __nv_bfloat16 g_sdth[(size_t)S_INT*H];
__device__ __align__(16) __nv_bfloat16 g_sdtl[(size_t)S_INT*H];
__device__ __align__(16) float g_ga[(size_t)N_TOK*S_INT];
__device__ __align__(16) float g_gb[(size_t)N_TOK*S_INT];
__device__ __align__(16) __nv_bfloat16 g_ah[(size_t)N_TOK*S_INT];
__device__ __align__(16) __nv_bfloat16 g_al[(size_t)N_TOK*S_INT];
__device__ __align__(16) float g_rg[(size_t)NP_MAX*D_EXP];
__device__ __align__(16) float g_ru[(size_t)NP_MAX*D_EXP];
__device__ __align__(16) __nv_bfloat16 g_rh[(size_t)NP_MAX*D_EXP];
__device__ __align__(16) __nv_bfloat16 g_rl[(size_t)NP_MAX*D_EXP];

// ---------------- PTX helpers (baseline ISA only: sm_80-level) ---------------
__device__ __forceinline__ uint32_t s2u(const void* p){
    uint32_t a;
    asm("{ .reg .u64 t; cvta.to.shared.u64 t, %1; cvt.u32.u64 %0, t; }" : "=r"(a) : "l"(p));
    return a;
}
__device__ __forceinline__ void cp16(uint32_t s, const void* g, int sz){
    asm volatile("cp.async.cg.shared.global [%0], [%1], 16, %2;" :: "r"(s), "l"(g), "r"(sz));
}
__device__ __forceinline__ void ldm4(uint32_t* r, uint32_t a){
    asm volatile("ldmatrix.sync.aligned.m8n8.x4.shared.b16 {%0,%1,%2,%3}, [%4];"
        : "=r"(r[0]), "=r"(r[1]), "=r"(r[2]), "=r"(r[3]) : "r"(a));
}
__device__ __forceinline__ void mma_bf16(float* c, const uint32_t* a, const uint32_t* b){
    asm volatile("mma.sync.aligned.m16n8k16.row.col.f32.bf16.bf16.f32 "
        "{%0,%1,%2,%3}, {%4,%5,%6,%7}, {%8,%9}, {%0,%1,%2,%3};"
        : "+f"(c[0]), "+f"(c[1]), "+f"(c[2]), "+f"(c[3])
        : "r"(a[0]), "r"(a[1]), "r"(a[2]), "r"(a[3]), "r"(b[0]), "r"(b[1]));
}

// ---------------- routing ----------------------------------------------------
__device__ __forceinline__ int expert_of(int t){
    t = t < 0 ? 0 : (t > VOCAB-1 ? VOCAB-1 : t);
    return t & (NEXP-1);
}
__global__ void k_reset(){
    int i = blockIdx.x*blockDim.x + threadIdx.x;
    if (i < NP_MAX) g_perm[i] = -1;
    if (i < NEXP){ g_counts[i] = 0; g_cursor[i] = 0; }
}
__global__ void k_hist(const int* __restrict__ tok){
    int i = blockIdx.x*blockDim.x + threadIdx.x;
    if (i < N_TOK) atomicAdd(&g_counts[expert_of(tok[i])], 1);
}
__global__ void k_off(){
    g_off[0] = 0;
    for (int e = 0; e < NEXP; e++)
        g_off[e+1] = g_off[e] + ((g_counts[e] + BM - 1)/BM)*BM;
}
__global__ void k_scatter(const int* __restrict__ tok){
    int i = blockIdx.x*blockDim.x + threadIdx.x;
    if (i < N_TOK){
        int e = expert_of(tok[i]);
        int p = atomicAdd(&g_cursor[e], 1);
        g_perm[g_off[e] + p] = i;
    }
}

// ---------------- split / transpose+split / silu+split -----------------------
__device__ __forceinline__ void split1(float v, __nv_bfloat16& h, __nv_bfloat16& l){
    h = __float2bfloat16(v);
    l = __float2bfloat16(v - __bfloat162float(h));
}
__global__ void k_split(const float* __restrict__ in, __nv_bfloat16* __restrict__ oh,
                        __nv_bfloat16* __restrict__ ol, int n4){
    int i = blockIdx.x*blockDim.x + threadIdx.x;
    if (i >= n4) return;
    float4 v = reinterpret_cast<const float4*>(in)[i];
    __nv_bfloat16 h0,h1,h2,h3,l0,l1,l2,l3;
    split1(v.x,h0,l0); split1(v.y,h1,l1); split1(v.z,h2,l2); split1(v.w,h3,l3);
    reinterpret_cast<__nv_bfloat162*>(oh)[2*i]   = __halves2bfloat162(h0,h1);
    reinterpret_cast<__nv_bfloat162*>(oh)[2*i+1] = __halves2bfloat162(h2,h3);
    reinterpret_cast<__nv_bfloat162*>(ol)[2*i]   = __halves2bfloat162(l0,l1);
    reinterpret_cast<__nv_bfloat162*>(ol)[2*i+1] = __halves2bfloat162(l2,l3);
}
// in [z][K][N] fp32 -> out_hi/out_lo [z][N][K] bf16
__global__ void k_split_t(const float* __restrict__ in, __nv_bfloat16* __restrict__ oh,
                          __nv_bfloat16* __restrict__ ol, int K, int N){
    __shared__ float t[32][33];
    size_t zo = (size_t)blockIdx.z * K * N;
    int n0 = blockIdx.x*32, k0 = blockIdx.y*32;
    int tx = threadIdx.x, ty = threadIdx.y;
    for (int j = ty; j < 32; j += 8)
        t[j][tx] = in[zo + (size_t)(k0+j)*N + n0 + tx];
    __syncthreads();
    for (int j = ty; j < 32; j += 8){
        float v = t[tx][j];
        __nv_bfloat16 h, l; split1(v, h, l);
        size_t o = zo + (size_t)(n0+j)*K + k0 + tx;
        oh[o] = h; ol[o] = l;
    }
}
__global__ void k_silu_split(const float* __restrict__ G, const float* __restrict__ U,
                             __nv_bfloat16* __restrict__ oh, __nv_bfloat16* __restrict__ ol, int n4){
    int i = blockIdx.x*blockDim.x + threadIdx.x;
    if (i >= n4) return;
    float4 g = reinterpret_cast<const float4*>(G)[i];
    float4 u = reinterpret_cast<const float4*>(U)[i];
    float s0 = g.x/(1.0f+__expf(-g.x))*u.x;
    float s1 = g.y/(1.0f+__expf(-g.y))*u.y;
    float s2 = g.z/(1.0f+__expf(-g.z))*u.z;
    float s3 = g.w/(1.0f+__expf(-g.w))*u.w;
    __nv_bfloat16 h0,h1,h2,h3,l0,l1,l2,l3;
    split1(s0,h0,l0); split1(s1,h1,l1); split1(s2,h2,l2); split1(s3,h3,l3);
    reinterpret_cast<__nv_bfloat162*>(oh)[2*i]   = __halves2bfloat162(h0,h1);
    reinterpret_cast<__nv_bfloat162*>(oh)[2*i+1] = __halves2bfloat162(h2,h3);
    reinterpret_cast<__nv_bfloat162*>(ol)[2*i]   = __halves2bfloat162(l0,l1);
    reinterpret_cast<__nv_bfloat162*>(ol)[2*i+1] = __halves2bfloat162(l2,l3);
}

// ---------------- HMMA GEMM: C[fp32] = (Ah+Al) @ (Bh+Bl)^T -------------------
// A: [rows,K] bf16 hi/lo; B: [Nslab,K] bf16 hi/lo (weights pre-transposed).
// 128x128x32 tiles, 3-stage cp.async pipeline, warp tile 32x64 (2x8 m16n8k16),
// 3 mma terms per frag pair: hi*hi + lo*hi + hi*lo.
template<bool GA, bool SC, bool EX>
__global__ void __launch_bounds__(256,1)
mma_gemm(const __nv_bfloat16* __restrict__ Ah, const __nv_bfloat16* __restrict__ Al,
         const __nv_bfloat16* __restrict__ Bh, const __nv_bfloat16* __restrict__ Bl,
         float* __restrict__ C, int Nw, int K)
{
    extern __shared__ __align__(16) char sm[];
    const int tid  = threadIdx.x, lane = tid & 31, wid = tid >> 5;
    const int wm   = wid & 3, wn = wid >> 2;          // 4x2 warp grid
    const int row0 = blockIdx.y*BM, col0 = blockIdx.x*BN;

    if (EX){
        if (row0 >= g_off[NEXP]) return;
        int e = 0;
#pragma unroll
        for (int i = 1; i < NEXP; i++) if (row0 >= g_off[i]) e = i;
        size_t so = (size_t)e * Nw * K;
        Bh += so; Bl += so;
    }

    // ---- cp.async load mapping: thread -> (row, 16 consecutive elements) ----
    const int lr = tid >> 1;
    const int lc = (tid & 1) * 16;
    size_t abase; int asz = 16;
    if (GA){
        int gr = g_perm[row0 + lr];
        asz   = gr >= 0 ? 16 : 0;
        abase = (size_t)(gr >= 0 ? gr : 0) * K;
    } else {
        abase = (size_t)(row0 + lr) * K;
    }
    const size_t bbase = (size_t)(col0 + lr) * K;
    const uint32_t smb = s2u(sm);
    const uint32_t sld = smb + (uint32_t)lr*LDSB + (uint32_t)lc*2;

    // ---- ldmatrix lane constants ----
    const int a_r  = lane & 15;
    const int a_cb = (lane >> 4) * 16;                      // byte offset in k
    const int b_r  = (lane & 7) + ((lane >> 4) * 8);
    const int b_cb = ((lane >> 3) & 1) * 16;

    float acc[2][8][4];
#pragma unroll
    for (int i = 0; i < 2; i++)
#pragma unroll
        for (int j = 0; j < 8; j++)
#pragma unroll
            for (int k = 0; k < 4; k++) acc[i][j][k] = 0.f;

    auto load_stage = [&](int c, int stg){
        const int k0 = c * BK;
        const uint32_t s = sld + (uint32_t)stg * STG_B;
        const __nv_bfloat16* pa = Ah + abase + k0 + lc;
        const __nv_bfloat16* qa = Al + abase + k0 + lc;
        const __nv_bfloat16* pb = Bh + bbase + k0 + lc;
        const __nv_bfloat16* qb = Bl + bbase + k0 + lc;
        cp16(s,            pa,     asz); cp16(s + 16,            pa + 8, asz);
        cp16(s +   TILE_B, qa,     asz); cp16(s +   TILE_B + 16, qa + 8, asz);
        cp16(s + 2*TILE_B, pb,     16);  cp16(s + 2*TILE_B + 16, pb + 8, 16);
        cp16(s + 3*TILE_B, qb,     16);  cp16(s + 3*TILE_B + 16, qb + 8, 16);
    };

    const int NCk = K / BK;
#pragma unroll
    for (int s = 0; s < NSTG; s++){
        load_stage(s, s);
        asm volatile("cp.async.commit_group;");
    }

    for (int c = 0; c < NCk; c++){
        asm volatile("cp.async.wait_group %0;" :: "n"(NSTG-1));
        __syncthreads();
        const uint32_t base = smb + (uint32_t)(c % NSTG) * STG_B;
#pragma unroll
        for (int ks = 0; ks < 2; ks++){
            uint32_t ah[2][4], al_[2][4], bh[4][4], bl_[4][4];
#pragma unroll
            for (int mt = 0; mt < 2; mt++){
                uint32_t ar = base + (uint32_t)(wm*32 + mt*16 + a_r)*LDSB + ks*32 + a_cb;
                ldm4(ah[mt],  ar);
                ldm4(al_[mt], ar + TILE_B);
            }
#pragma unroll
            for (int np = 0; np < 4; np++){
                uint32_t br = base + 2*TILE_B + (uint32_t)(wn*64 + np*16 + b_r)*LDSB + ks*32 + b_cb;
                ldm4(bh[np],  br);
                ldm4(bl_[np], br + TILE_B);
            }
#pragma unroll
            for (int mt = 0; mt < 2; mt++)
#pragma unroll
                for (int np = 0; np < 4; np++){
                    mma_bf16(acc[mt][2*np],   ah[mt],  &bh[np][0]);
                    mma_bf16(acc[mt][2*np+1], ah[mt],  &bh[np][2]);
                    mma_bf16(acc[mt][2*np],   al_[mt], &bh[np][0]);
                    mma_bf16(acc[mt][2*np+1], al_[mt], &bh[np][2]);
                    mma_bf16(acc[mt][2*np],   ah[mt],  &bl_[np][0]);
                    mma_bf16(acc[mt][2*np+1], ah[mt],  &bl_[np][2]);
                }
        }
        __syncthreads();
        if (c + NSTG < NCk) load_stage(c + NSTG, (c + NSTG) % NSTG);
        asm volatile("cp.async.commit_group;");   // uniform group accounting
    }

    // ---- epilogue ----
    const int er0 = row0 + wm*32 + (lane >> 2);
    const int ec  = col0 + wn*64 + (lane & 3)*2;
#pragma unroll
    for (int mt = 0; mt < 2; mt++){
#pragma unroll
        for (int hf = 0; hf < 2; hf++){
            int r = er0 + mt*16 + hf*8;
            int orow = r; bool wr = true;
            if (SC){ int gr = g_perm[r]; wr = gr >= 0; orow = wr ? gr : 0; }
            if (wr){
                float* Cp = C + (size_t)orow * Nw + ec;
#pragma unroll
                for (int nt = 0; nt < 8; nt++){
                    float2 v = make_float2(acc[mt][nt][hf*2], acc[mt][nt][hf*2+1]);
                    float2* d = reinterpret_cast<float2*>(Cp + nt*8);
                    if (SC){ float2 o = *d; v.x += o.x; v.y += o.y; }
                    *d = v;
                }
            }
        }
    }
}

// ---------------- launch ------------------------------------------------------
extern "C" void kernel_launch(void* const* d_in, const int* in_sizes, int n_in,
                              void* d_out, int out_size)
{
    const float* x   = (const float*)d_in[0];
    const int*   tok = (const int*)d_in[1];
    const float* gw  = (const float*)d_in[2];   // [8,1024,512]
    const float* uw  = (const float*)d_in[3];   // [8,1024,512]
    const float* dw  = (const float*)d_in[4];   // [8,512,1024]
    const float* sgw = (const float*)d_in[5];   // [1024,1024]
    const float* suw = (const float*)d_in[6];   // [1024,1024]
    const float* sdw = (const float*)d_in[7];   // [1024,1024]
    float* out = (float*)d_out;

    cudaFuncSetAttribute(mma_gemm<false,false,false>, cudaFuncAttributeMaxDynamicSharedMemorySize, SMEM_BYTES);
    cudaFuncSetAttribute(mma_gemm<true,false,true>,   cudaFuncAttributeMaxDynamicSharedMemorySize, SMEM_BYTES);
    cudaFuncSetAttribute(mma_gemm<false,true,true>,   cudaFuncAttributeMaxDynamicSharedMemorySize, SMEM_BYTES);

    __nv_bfloat16 *xh,*xl,*gth,*gtl,*uth,*utl,*dth,*dtl,*sgth,*sgtl,*suth,*sutl,*sdth,*sdtl,*ah,*al,*rh,*rl;
    float *ga,*gb,*rg,*ru;
    cudaGetSymbolAddress((void**)&xh, g_xh);   cudaGetSymbolAddress((void**)&xl, g_xl);
    cudaGetSymbolAddress((void**)&gth, g_gth); cudaGetSymbolAddress((void**)&gtl, g_gtl);
    cudaGetSymbolAddress((void**)&uth, g_uth); cudaGetSymbolAddress((void**)&utl, g_utl);
    cudaGetSymbolAddress((void**)&dth, g_dth); cudaGetSymbolAddress((void**)&dtl, g_dtl);
    cudaGetSymbolAddress((void**)&sgth, g_sgth); cudaGetSymbolAddress((void**)&sgtl, g_sgtl);
    cudaGetSymbolAddress((void**)&suth, g_suth); cudaGetSymbolAddress((void**)&sutl, g_sutl);
    cudaGetSymbolAddress((void**)&sdth, g_sdth); cudaGetSymbolAddress((void**)&sdtl, g_sdtl);
    cudaGetSymbolAddress((void**)&ah, g_ah);   cudaGetSymbolAddress((void**)&al, g_al);
    cudaGetSymbolAddress((void**)&rh, g_rh);   cudaGetSymbolAddress((void**)&rl, g_rl);
    cudaGetSymbolAddress((void**)&ga, g_ga);   cudaGetSymbolAddress((void**)&gb, g_gb);
    cudaGetSymbolAddress((void**)&rg, g_rg);   cudaGetSymbolAddress((void**)&ru, g_ru);

    // routing
    k_reset<<<(NP_MAX+255)/256, 256>>>();
    k_hist<<<(N_TOK+255)/256, 256>>>(tok);
    k_off<<<1,1>>>();
    k_scatter<<<(N_TOK+255)/256, 256>>>(tok);

    // operand preparation: split x; transpose+split weights to [N,K]
    k_split<<<(N_TOK*H/4+255)/256, 256>>>(x, xh, xl, N_TOK*H/4);
    k_split_t<<<dim3(D_EXP/32, H/32, NEXP), dim3(32,8)>>>(gw, gth, gtl, H, D_EXP);
    k_split_t<<<dim3(D_EXP/32, H/32, NEXP), dim3(32,8)>>>(uw, uth, utl, H, D_EXP);
    k_split_t<<<dim3(H/32, D_EXP/32, NEXP), dim3(32,8)>>>(dw, dth, dtl, D_EXP, H);
    k_split_t<<<dim3(S_INT/32, H/32, 1), dim3(32,8)>>>(sgw, sgth, sgtl, H, S_INT);
    k_split_t<<<dim3(S_INT/32, H/32, 1), dim3(32,8)>>>(suw, suth, sutl, H, S_INT);
    k_split_t<<<dim3(H/32, S_INT/32, 1), dim3(32,8)>>>(sdw, sdth, sdtl, S_INT, H);

    // shared branch
    dim3 g1(S_INT/BN, N_TOK/BM);
    mma_gemm<false,false,false><<<g1, 256, SMEM_BYTES>>>(xh, xl, sgth, sgtl, ga, S_INT, H);
    mma_gemm<false,false,false><<<g1, 256, SMEM_BYTES>>>(xh, xl, suth, sutl, gb, S_INT, H);
    k_silu_split<<<(N_TOK*S_INT/4+255)/256, 256>>>(ga, gb, ah, al, N_TOK*S_INT/4);
    dim3 g2(H/BN, N_TOK/BM);
    mma_gemm<false,false,false><<<g2, 256, SMEM_BYTES>>>(ah, al, sdth, sdtl, out, H, S_INT);

    // routed branch (expert-grouped padded rows)
    dim3 g3(D_EXP/BN, NP_MAX/BM);
    mma_gemm<true,false,true><<<g3, 256, SMEM_BYTES>>>(xh, xl, gth, gtl, rg, D_EXP, H);
    mma_gemm<true,false,true><<<g3, 256, SMEM_BYTES>>>(xh, xl, uth, utl, ru, D_EXP, H);
    k_silu_split<<<(NP_MAX*D_EXP/4+255)/256, 256>>>(rg, ru, rh, rl, NP_MAX*D_EXP/4);
    dim3 g4(H/BN, NP_MAX/BM);
    mma_gemm<false,true,true><<<g4, 256, SMEM_BYTES>>>(rh, rl, dth, dtl, out, H, D_EXP);
}